// round 5
// baseline (speedup 1.0000x reference)
#include <cuda_runtime.h>
#include <cuda_bf16.h>

#define B_DIM 128
#define N_DIM 256
#define RSW   129                  // P row stride in 32-bit words (128 bf16x2 + 1 pad)
#define ITERS 50
#define NTHR  512

__device__ float g_ndcg[B_DIM];
__device__ int   g_valid[B_DIM];

// bf16 (stored in low/high 16 bits of a word) -> fp32, pure ALU ops
__device__ __forceinline__ float bf_lo(unsigned w) { return __int_as_float(w << 16); }
__device__ __forceinline__ float bf_hi(unsigned w) { return __int_as_float(w & 0xffff0000u); }

// ------------------------------------------------------------- mega kernel ---
// One CTA per batch, 512 threads. P stored bf16 in smem with padded rows.
// Sinkhorn on diagonal scalings (u,v); column pass thread-per-column-pair over a
// 64-row quarter; row pass thread-per-half-row. fp32 math, ALU-only unpack.
__global__ void __launch_bounds__(NTHR, 1)
mega_kernel(const float* __restrict__ yp, const int* __restrict__ ytr) {
    extern __shared__ unsigned smw[];
    unsigned* Ph = smw;                          // 256*129 words (bf16 P)
    float* s   = (float*)(Ph + N_DIM * RSW);
    float* Bm  = s   + N_DIM;
    float* gA  = Bm  + N_DIM;
    float* u   = gA  + N_DIM;
    float* v   = u   + N_DIM;
    float* w   = v   + N_DIM;
    float* sp4 = w   + N_DIM;                    // 1024 column partials (4 quarters)
    float* rp  = sp4 + 4 * N_DIM;                // 512 row partials
    float* red = rp  + NTHR;                     // 32 words (also minmax scratch)
    int*   ei  = (int*)(red + 32);               // 256
    int*   shf = ei + N_DIM;                     // 1 word

    const int tid  = threadIdx.x;
    const int b    = blockIdx.x;
    const int lane = tid & 31;
    const int wid  = tid >> 5;

    // ---- fused global min/max of y_true (each CTA scans all 128KB, L2-hot) ----
    {
        const int4* t4 = (const int4*)ytr;
        unsigned umx = 0u, umn = 0u;
        #pragma unroll
        for (int k = 0; k < (B_DIM * N_DIM / 4) / NTHR; k++) {
            int4 x = t4[tid + k * NTHR];
            unsigned u0 = (unsigned)x.x ^ 0x80000000u;
            unsigned u1 = (unsigned)x.y ^ 0x80000000u;
            unsigned u2 = (unsigned)x.z ^ 0x80000000u;
            unsigned u3 = (unsigned)x.w ^ 0x80000000u;
            umx = max(umx, max(max(u0, u1), max(u2, u3)));
            umn = max(umn, max(max(~u0, ~u1), max(~u2, ~u3)));
        }
        for (int o = 16; o; o >>= 1) {
            umx = max(umx, __shfl_xor_sync(0xffffffffu, umx, o));
            umn = max(umn, __shfl_xor_sync(0xffffffffu, umn, o));
        }
        unsigned* ur = (unsigned*)red;
        if (lane == 0) { ur[wid] = umx; ur[16 + wid] = umn; }
        __syncthreads();
        if (tid == 0) {
            for (int k = 1; k < 16; k++) { umx = max(umx, ur[k]); umn = max(umn, ur[16 + k]); }
            int mxv = (int)(umx ^ 0x80000000u);
            int mnv = (int)((~umn) ^ 0x80000000u);
            shf[0] = mxv + mnv;
        }
        __syncthreads();
    }
    const int shift = shf[0];

    // ---- setup: scores, flipped relevancy, gains (threads 0..255) ----
    float sj = 0.f, gain = 0.f; int e = 0;
    if (tid < 256) {
        sj = yp[b * N_DIM + tid];
        s[tid] = sj;
        e = shift - ytr[b * N_DIM + tid];
        e = min(max(e, 0), 30);
        ei[tid] = e;
        gain = (float)((1u << e) - 1u);
        gA[tid] = gain;
        u[tid] = 1.0f;
    }
    __syncthreads();

    // ---- B_mat[j] = sum_k |s_j - s_k| (Kahan) + IDCG via stable rank ----
    float idcg = 0.f;
    if (tid < 256) {
        float bsum = 0.f, bc = 0.f;
        int pos = 0;
        for (int k = 0; k < N_DIM; k++) {
            float d  = fabsf(sj - s[k]);
            float y  = d - bc;
            float t2 = bsum + y;
            bc = (t2 - bsum) - y;
            bsum = t2;
            int ek = ei[k];
            pos += (ek > e) ? 1 : 0;
            pos += ((k < tid) && (ek == e)) ? 1 : 0;
        }
        Bm[tid] = bsum;
        float x = gain / log2f((float)(pos + 2));
        for (int o = 16; o; o >>= 1) x += __shfl_xor_sync(0xffffffffu, x, o);
        if (lane == 0) red[wid] = x;
    }
    __syncthreads();
    if (tid == 0) {
        for (int k = 0; k < 8; k++) idcg += red[k];
    }

    // ---- build P (bf16): row i = softmax_j(s_j*(255-2i) - Bm_j), tau=1 ----
    __nv_bfloat16* Phb = (__nv_bfloat16*)Ph;
    for (int i = wid; i < N_DIM; i += 16) {
        float sc = (float)(255 - 2 * i);
        float lg[8], ev[8];
        float mxl = -3.4e38f;
        #pragma unroll
        for (int k = 0; k < 8; k++) {
            int j = k * 32 + lane;
            float l = fmaf(s[j], sc, -Bm[j]);
            lg[k] = l;
            mxl = fmaxf(mxl, l);
        }
        for (int o = 16; o; o >>= 1) mxl = fmaxf(mxl, __shfl_xor_sync(0xffffffffu, mxl, o));
        float ssum = 0.f;
        #pragma unroll
        for (int k = 0; k < 8; k++) { float ex = expf(lg[k] - mxl); ev[k] = ex; ssum += ex; }
        for (int o = 16; o; o >>= 1) ssum += __shfl_xor_sync(0xffffffffu, ssum, o);
        float inv = 1.0f / ssum;
        __nv_bfloat16* row = Phb + i * (2 * RSW);
        #pragma unroll
        for (int k = 0; k < 8; k++) row[k * 32 + lane] = __float2bfloat16_rn(ev[k] * inv);
    }
    __syncthreads();

    // ---- Sinkhorn with early exit ----
    const int p = tid & 127;                 // column pair (cols 2p, 2p+1)
    const int q = tid >> 7;                  // row quarter (64 rows)
    const unsigned* colp = Ph + (q * 64) * RSW + p;
    const float* uq = u + q * 64;
    const int ir = tid & 255;                // row for row pass
    const int h  = tid >> 8;                 // column half (128 cols)
    const unsigned* rowp = Ph + ir * RSW + h * 64;
    const float* vh = v + h * 128;
    float vprev = 0.f;

    for (int it = 0; it < ITERS; it++) {
        // column pass: partial over 64 rows for cols (2p, 2p+1)
        float a0 = 0.f, a1 = 0.f, a2 = 0.f, a3 = 0.f;
        #pragma unroll
        for (int i4 = 0; i4 < 16; i4++) {
            float4 uu = *(const float4*)(uq + 4 * i4);
            unsigned w0 = colp[(4 * i4 + 0) * RSW];
            unsigned w1 = colp[(4 * i4 + 1) * RSW];
            unsigned w2 = colp[(4 * i4 + 2) * RSW];
            unsigned w3 = colp[(4 * i4 + 3) * RSW];
            a0 = fmaf(bf_lo(w0), uu.x, a0); a1 = fmaf(bf_hi(w0), uu.x, a1);
            a2 = fmaf(bf_lo(w1), uu.y, a2); a3 = fmaf(bf_hi(w1), uu.y, a3);
            a0 = fmaf(bf_lo(w2), uu.z, a0); a1 = fmaf(bf_hi(w2), uu.z, a1);
            a2 = fmaf(bf_lo(w3), uu.w, a2); a3 = fmaf(bf_hi(w3), uu.w, a3);
        }
        ((float2*)(sp4 + q * 256))[p] = make_float2(a0 + a2, a1 + a3);
        __syncthreads();

        // v update + convergence flag (threads 0..255)
        int ch = 0;
        if (tid < 256) {
            float S = (sp4[tid] + sp4[256 + tid]) + (sp4[512 + tid] + sp4[768 + tid]);
            float vn = 1.0f / fmaxf(S, 1e-10f);
            v[tid] = vn;
            ch = (fabsf(vn - vprev) > 1e-5f * fabsf(vprev)) ? 1 : 0;
            vprev = vn;
        }
        if (__syncthreads_or(ch) == 0) break;   // fixed point: remaining iters inert

        // row pass: half-row dot with v
        float r0 = 0.f, r1 = 0.f, r2 = 0.f, r3 = 0.f;
        #pragma unroll
        for (int j4 = 0; j4 < 16; j4++) {
            float4 v0 = *(const float4*)(vh + 8 * j4);
            float4 v1 = *(const float4*)(vh + 8 * j4 + 4);
            unsigned w0 = rowp[4 * j4 + 0];
            unsigned w1 = rowp[4 * j4 + 1];
            unsigned w2 = rowp[4 * j4 + 2];
            unsigned w3 = rowp[4 * j4 + 3];
            r0 = fmaf(bf_lo(w0), v0.x, r0); r1 = fmaf(bf_hi(w0), v0.y, r1);
            r2 = fmaf(bf_lo(w1), v0.z, r2); r3 = fmaf(bf_hi(w1), v0.w, r3);
            r0 = fmaf(bf_lo(w2), v1.x, r0); r1 = fmaf(bf_hi(w2), v1.y, r1);
            r2 = fmaf(bf_lo(w3), v1.z, r2); r3 = fmaf(bf_hi(w3), v1.w, r3);
        }
        rp[tid] = (r0 + r1) + (r2 + r3);
        __syncthreads();

        if (tid < 256) u[tid] = 1.0f / fmaxf(rp[tid] + rp[256 + tid], 1e-10f);
        __syncthreads();
    }

    // ---- final: num = sum_i disc_i * u_i * (P[i] . (v*g)) ----
    if (tid < 256) w[tid] = v[tid] * gA[tid];
    __syncthreads();
    {
        float r0 = 0.f, r1 = 0.f, r2 = 0.f, r3 = 0.f;
        const float* wh = w + h * 128;
        #pragma unroll
        for (int j4 = 0; j4 < 16; j4++) {
            float4 v0 = *(const float4*)(wh + 8 * j4);
            float4 v1 = *(const float4*)(wh + 8 * j4 + 4);
            unsigned w0 = rowp[4 * j4 + 0];
            unsigned w1 = rowp[4 * j4 + 1];
            unsigned w2 = rowp[4 * j4 + 2];
            unsigned w3 = rowp[4 * j4 + 3];
            r0 = fmaf(bf_lo(w0), v0.x, r0); r1 = fmaf(bf_hi(w0), v0.y, r1);
            r2 = fmaf(bf_lo(w1), v0.z, r2); r3 = fmaf(bf_hi(w1), v0.w, r3);
            r0 = fmaf(bf_lo(w2), v1.x, r0); r1 = fmaf(bf_hi(w2), v1.y, r1);
            r2 = fmaf(bf_lo(w3), v1.z, r2); r3 = fmaf(bf_hi(w3), v1.w, r3);
        }
        rp[tid] = (r0 + r1) + (r2 + r3);
    }
    __syncthreads();
    if (tid < 256) {
        float val = u[tid] * (rp[tid] + rp[256 + tid]) / log2f((float)(tid + 2));
        for (int o = 16; o; o >>= 1) val += __shfl_xor_sync(0xffffffffu, val, o);
        if (lane == 0) red[wid] = val;
    }
    __syncthreads();
    if (tid == 0) {
        float num = 0.f;
        for (int k = 0; k < 8; k++) num += red[k];
        bool valid = (idcg != 0.0f);
        g_ndcg[b]  = valid ? (num / (idcg + 1e-10f)) : 0.0f;
        g_valid[b] = valid ? 1 : 0;
    }
}

// ---------------------------------------------------------------- finalize ---
__global__ void final_kernel(float* __restrict__ out) {
    int tid = threadIdx.x;           // 128 threads
    __shared__ float rs[4];
    __shared__ int   rc[4];
    float x = g_ndcg[tid];
    int   c = g_valid[tid];
    for (int o = 16; o; o >>= 1) {
        x += __shfl_xor_sync(0xffffffffu, x, o);
        c += __shfl_xor_sync(0xffffffffu, c, o);
    }
    int lane = tid & 31, wid = tid >> 5;
    if (lane == 0) { rs[wid] = x; rc[wid] = c; }
    __syncthreads();
    if (tid == 0) {
        float sum = 0.f; int cnt = 0;
        for (int k = 0; k < 4; k++) { sum += rs[k]; cnt += rc[k]; }
        out[0] = (cnt > 0) ? (-(sum / (float)cnt)) : 0.0f;
    }
}

// ------------------------------------------------------------------ launch ---
extern "C" void kernel_launch(void* const* d_in, const int* in_sizes, int n_in,
                              void* d_out, int out_size) {
    const float* yp  = (const float*)d_in[0];
    const int*   ytr = (const int*)d_in[1];
    float*       out = (float*)d_out;

    // P + 6 vectors + sp4 + rp + red + ei + shf(pad 8)
    size_t smem = (size_t)(N_DIM * RSW + 6 * N_DIM + 4 * N_DIM + NTHR + 32 + N_DIM + 8) * 4;
    cudaFuncSetAttribute(mega_kernel, cudaFuncAttributeMaxDynamicSharedMemorySize, (int)smem);

    mega_kernel<<<B_DIM, NTHR, smem>>>(yp, ytr);
    final_kernel<<<1, 128>>>(out);
}

// round 6
// speedup vs baseline: 1.0037x; 1.0037x over previous
#include <cuda_runtime.h>
#include <cuda_bf16.h>

#define B_DIM 128
#define N_DIM 256
#define RSW   129                  // P row stride in 32-bit words (128 bf16x2 + 1 pad)
#define ITERS 50
#define NTHR  512

__device__ float g_ndcg[B_DIM];
__device__ int   g_valid[B_DIM];

// bf16 (stored in low/high 16 bits of a word) -> fp32, pure ALU ops
__device__ __forceinline__ float bf_lo(unsigned w) { return __int_as_float(w << 16); }
__device__ __forceinline__ float bf_hi(unsigned w) { return __int_as_float(w & 0xffff0000u); }

// ------------------------------------------------------------- mega kernel ---
// One CTA per batch, 512 threads. P stored bf16 in smem with padded rows.
// Sinkhorn on diagonal scalings (u,v); column pass thread-per-column-pair over a
// 64-row quarter; row pass thread-per-half-row. fp32 math, ALU-only unpack.
__global__ void __launch_bounds__(NTHR, 1)
mega_kernel(const float* __restrict__ yp, const int* __restrict__ ytr) {
    extern __shared__ unsigned smw[];
    unsigned* Ph = smw;                          // 256*129 words (bf16 P)
    float* s   = (float*)(Ph + N_DIM * RSW);
    float* Bm  = s   + N_DIM;
    float* gA  = Bm  + N_DIM;
    float* u   = gA  + N_DIM;
    float* v   = u   + N_DIM;
    float* w   = v   + N_DIM;
    float* sp4 = w   + N_DIM;                    // 1024 column partials (4 quarters)
    float* rp  = sp4 + 4 * N_DIM;                // 512 row partials
    float* red = rp  + NTHR;                     // 32 words (also minmax scratch)
    int*   ei  = (int*)(red + 32);               // 256
    int*   shf = ei + N_DIM;                     // 1 word

    const int tid  = threadIdx.x;
    const int b    = blockIdx.x;
    const int lane = tid & 31;
    const int wid  = tid >> 5;

    // ---- fused global min/max of y_true (each CTA scans all 128KB, L2-hot) ----
    {
        const int4* t4 = (const int4*)ytr;
        unsigned umx = 0u, umn = 0u;
        #pragma unroll
        for (int k = 0; k < (B_DIM * N_DIM / 4) / NTHR; k++) {
            int4 x = t4[tid + k * NTHR];
            unsigned u0 = (unsigned)x.x ^ 0x80000000u;
            unsigned u1 = (unsigned)x.y ^ 0x80000000u;
            unsigned u2 = (unsigned)x.z ^ 0x80000000u;
            unsigned u3 = (unsigned)x.w ^ 0x80000000u;
            umx = max(umx, max(max(u0, u1), max(u2, u3)));
            umn = max(umn, max(max(~u0, ~u1), max(~u2, ~u3)));
        }
        for (int o = 16; o; o >>= 1) {
            umx = max(umx, __shfl_xor_sync(0xffffffffu, umx, o));
            umn = max(umn, __shfl_xor_sync(0xffffffffu, umn, o));
        }
        unsigned* ur = (unsigned*)red;
        if (lane == 0) { ur[wid] = umx; ur[16 + wid] = umn; }
        __syncthreads();
        if (tid == 0) {
            for (int k = 1; k < 16; k++) { umx = max(umx, ur[k]); umn = max(umn, ur[16 + k]); }
            int mxv = (int)(umx ^ 0x80000000u);
            int mnv = (int)((~umn) ^ 0x80000000u);
            shf[0] = mxv + mnv;
        }
        __syncthreads();
    }
    const int shift = shf[0];

    // ---- setup: scores, flipped relevancy, gains (threads 0..255) ----
    float sj = 0.f, gain = 0.f; int e = 0;
    if (tid < 256) {
        sj = yp[b * N_DIM + tid];
        s[tid] = sj;
        e = shift - ytr[b * N_DIM + tid];
        e = min(max(e, 0), 30);
        ei[tid] = e;
        gain = (float)((1u << e) - 1u);
        gA[tid] = gain;
        u[tid] = 1.0f;
    }
    __syncthreads();

    // ---- B_mat[j] = sum_k |s_j - s_k| (Kahan) + IDCG via stable rank ----
    float idcg = 0.f;
    if (tid < 256) {
        float bsum = 0.f, bc = 0.f;
        int pos = 0;
        for (int k = 0; k < N_DIM; k++) {
            float d  = fabsf(sj - s[k]);
            float y  = d - bc;
            float t2 = bsum + y;
            bc = (t2 - bsum) - y;
            bsum = t2;
            int ek = ei[k];
            pos += (ek > e) ? 1 : 0;
            pos += ((k < tid) && (ek == e)) ? 1 : 0;
        }
        Bm[tid] = bsum;
        float x = gain / log2f((float)(pos + 2));
        for (int o = 16; o; o >>= 1) x += __shfl_xor_sync(0xffffffffu, x, o);
        if (lane == 0) red[wid] = x;
    }
    __syncthreads();
    if (tid == 0) {
        for (int k = 0; k < 8; k++) idcg += red[k];
    }

    // ---- build P (bf16): row i = softmax_j(s_j*(255-2i) - Bm_j), tau=1 ----
    __nv_bfloat16* Phb = (__nv_bfloat16*)Ph;
    for (int i = wid; i < N_DIM; i += 16) {
        float sc = (float)(255 - 2 * i);
        float lg[8], ev[8];
        float mxl = -3.4e38f;
        #pragma unroll
        for (int k = 0; k < 8; k++) {
            int j = k * 32 + lane;
            float l = fmaf(s[j], sc, -Bm[j]);
            lg[k] = l;
            mxl = fmaxf(mxl, l);
        }
        for (int o = 16; o; o >>= 1) mxl = fmaxf(mxl, __shfl_xor_sync(0xffffffffu, mxl, o));
        float ssum = 0.f;
        #pragma unroll
        for (int k = 0; k < 8; k++) { float ex = expf(lg[k] - mxl); ev[k] = ex; ssum += ex; }
        for (int o = 16; o; o >>= 1) ssum += __shfl_xor_sync(0xffffffffu, ssum, o);
        float inv = 1.0f / ssum;
        __nv_bfloat16* row = Phb + i * (2 * RSW);
        #pragma unroll
        for (int k = 0; k < 8; k++) row[k * 32 + lane] = __float2bfloat16_rn(ev[k] * inv);
    }
    __syncthreads();

    // ---- Sinkhorn with early exit ----
    const int p = tid & 127;                 // column pair (cols 2p, 2p+1)
    const int q = tid >> 7;                  // row quarter (64 rows)
    const unsigned* colp = Ph + (q * 64) * RSW + p;
    const float* uq = u + q * 64;
    const int ir = tid & 255;                // row for row pass
    const int h  = tid >> 8;                 // column half (128 cols)
    const unsigned* rowp = Ph + ir * RSW + h * 64;
    const float* vh = v + h * 128;
    float vprev = 0.f;

    for (int it = 0; it < ITERS; it++) {
        // column pass: partial over 64 rows for cols (2p, 2p+1)
        float a0 = 0.f, a1 = 0.f, a2 = 0.f, a3 = 0.f;
        #pragma unroll
        for (int i4 = 0; i4 < 16; i4++) {
            float4 uu = *(const float4*)(uq + 4 * i4);
            unsigned w0 = colp[(4 * i4 + 0) * RSW];
            unsigned w1 = colp[(4 * i4 + 1) * RSW];
            unsigned w2 = colp[(4 * i4 + 2) * RSW];
            unsigned w3 = colp[(4 * i4 + 3) * RSW];
            a0 = fmaf(bf_lo(w0), uu.x, a0); a1 = fmaf(bf_hi(w0), uu.x, a1);
            a2 = fmaf(bf_lo(w1), uu.y, a2); a3 = fmaf(bf_hi(w1), uu.y, a3);
            a0 = fmaf(bf_lo(w2), uu.z, a0); a1 = fmaf(bf_hi(w2), uu.z, a1);
            a2 = fmaf(bf_lo(w3), uu.w, a2); a3 = fmaf(bf_hi(w3), uu.w, a3);
        }
        ((float2*)(sp4 + q * 256))[p] = make_float2(a0 + a2, a1 + a3);
        __syncthreads();

        // v update + convergence flag (threads 0..255)
        int ch = 0;
        if (tid < 256) {
            float S = (sp4[tid] + sp4[256 + tid]) + (sp4[512 + tid] + sp4[768 + tid]);
            float vn = 1.0f / fmaxf(S, 1e-10f);
            v[tid] = vn;
            ch = (fabsf(vn - vprev) > 1e-5f * fabsf(vprev)) ? 1 : 0;
            vprev = vn;
        }
        if (__syncthreads_or(ch) == 0) break;   // fixed point: remaining iters inert

        // row pass: half-row dot with v
        float r0 = 0.f, r1 = 0.f, r2 = 0.f, r3 = 0.f;
        #pragma unroll
        for (int j4 = 0; j4 < 16; j4++) {
            float4 v0 = *(const float4*)(vh + 8 * j4);
            float4 v1 = *(const float4*)(vh + 8 * j4 + 4);
            unsigned w0 = rowp[4 * j4 + 0];
            unsigned w1 = rowp[4 * j4 + 1];
            unsigned w2 = rowp[4 * j4 + 2];
            unsigned w3 = rowp[4 * j4 + 3];
            r0 = fmaf(bf_lo(w0), v0.x, r0); r1 = fmaf(bf_hi(w0), v0.y, r1);
            r2 = fmaf(bf_lo(w1), v0.z, r2); r3 = fmaf(bf_hi(w1), v0.w, r3);
            r0 = fmaf(bf_lo(w2), v1.x, r0); r1 = fmaf(bf_hi(w2), v1.y, r1);
            r2 = fmaf(bf_lo(w3), v1.z, r2); r3 = fmaf(bf_hi(w3), v1.w, r3);
        }
        rp[tid] = (r0 + r1) + (r2 + r3);
        __syncthreads();

        if (tid < 256) u[tid] = 1.0f / fmaxf(rp[tid] + rp[256 + tid], 1e-10f);
        __syncthreads();
    }

    // ---- final: num = sum_i disc_i * u_i * (P[i] . (v*g)) ----
    if (tid < 256) w[tid] = v[tid] * gA[tid];
    __syncthreads();
    {
        float r0 = 0.f, r1 = 0.f, r2 = 0.f, r3 = 0.f;
        const float* wh = w + h * 128;
        #pragma unroll
        for (int j4 = 0; j4 < 16; j4++) {
            float4 v0 = *(const float4*)(wh + 8 * j4);
            float4 v1 = *(const float4*)(wh + 8 * j4 + 4);
            unsigned w0 = rowp[4 * j4 + 0];
            unsigned w1 = rowp[4 * j4 + 1];
            unsigned w2 = rowp[4 * j4 + 2];
            unsigned w3 = rowp[4 * j4 + 3];
            r0 = fmaf(bf_lo(w0), v0.x, r0); r1 = fmaf(bf_hi(w0), v0.y, r1);
            r2 = fmaf(bf_lo(w1), v0.z, r2); r3 = fmaf(bf_hi(w1), v0.w, r3);
            r0 = fmaf(bf_lo(w2), v1.x, r0); r1 = fmaf(bf_hi(w2), v1.y, r1);
            r2 = fmaf(bf_lo(w3), v1.z, r2); r3 = fmaf(bf_hi(w3), v1.w, r3);
        }
        rp[tid] = (r0 + r1) + (r2 + r3);
    }
    __syncthreads();
    if (tid < 256) {
        float val = u[tid] * (rp[tid] + rp[256 + tid]) / log2f((float)(tid + 2));
        for (int o = 16; o; o >>= 1) val += __shfl_xor_sync(0xffffffffu, val, o);
        if (lane == 0) red[wid] = val;
    }
    __syncthreads();
    if (tid == 0) {
        float num = 0.f;
        for (int k = 0; k < 8; k++) num += red[k];
        bool valid = (idcg != 0.0f);
        g_ndcg[b]  = valid ? (num / (idcg + 1e-10f)) : 0.0f;
        g_valid[b] = valid ? 1 : 0;
    }
}

// ---------------------------------------------------------------- finalize ---
__global__ void final_kernel(float* __restrict__ out) {
    int tid = threadIdx.x;           // 128 threads
    __shared__ float rs[4];
    __shared__ int   rc[4];
    float x = g_ndcg[tid];
    int   c = g_valid[tid];
    for (int o = 16; o; o >>= 1) {
        x += __shfl_xor_sync(0xffffffffu, x, o);
        c += __shfl_xor_sync(0xffffffffu, c, o);
    }
    int lane = tid & 31, wid = tid >> 5;
    if (lane == 0) { rs[wid] = x; rc[wid] = c; }
    __syncthreads();
    if (tid == 0) {
        float sum = 0.f; int cnt = 0;
        for (int k = 0; k < 4; k++) { sum += rs[k]; cnt += rc[k]; }
        out[0] = (cnt > 0) ? (-(sum / (float)cnt)) : 0.0f;
    }
}

// ------------------------------------------------------------------ launch ---
extern "C" void kernel_launch(void* const* d_in, const int* in_sizes, int n_in,
                              void* d_out, int out_size) {
    const float* yp  = (const float*)d_in[0];
    const int*   ytr = (const int*)d_in[1];
    float*       out = (float*)d_out;

    // P + 6 vectors + sp4 + rp + red + ei + shf(pad 8)
    size_t smem = (size_t)(N_DIM * RSW + 6 * N_DIM + 4 * N_DIM + NTHR + 32 + N_DIM + 8) * 4;
    cudaFuncSetAttribute(mega_kernel, cudaFuncAttributeMaxDynamicSharedMemorySize, (int)smem);

    mega_kernel<<<B_DIM, NTHR, smem>>>(yp, ytr);
    final_kernel<<<1, 128>>>(out);
}

// round 8
// speedup vs baseline: 1.0158x; 1.0120x over previous
#include <cuda_runtime.h>
#include <cuda_bf16.h>

#define B_DIM 128
#define N_DIM 256
#define RSW   129                  // P row stride in 32-bit words (128 bf16x2 + 1 pad)
#define ITERS 50
#define NTHR  512

// ---- smem word offsets ----
#define W_PH   0                       // 33024 : P bf16 padded rows
#define W_S    33024
#define W_BM   33280
#define W_GA   33536
#define W_U    33792
#define W_V    34048
#define W_W    34304
#define W_SP   34560                   // 1024 column partials
#define W_RP   35584                   // 512 row partials
#define W_RED  36096                   // 32
#define W_EI   36128                   // 256
#define W_PW   36384                   // 8*256 : r^k tables, k=0..7
#define W_AN   38432                   // 32*256 : fp32 anchor rows (unnormalized softmax)
#define SMEM_WORDS (W_AN + 32*256)     // 46624 words = 186496 B

__device__ float    g_sum = 0.f;
__device__ int      g_cnt = 0;
__device__ unsigned g_tk  = 0u;

__device__ __forceinline__ float bf_lo(unsigned w) { return __int_as_float(w << 16); }
__device__ __forceinline__ float bf_hi(unsigned w) { return __int_as_float(w & 0xffff0000u); }

// ------------------------------------------------------------- mega kernel ---
__global__ void __launch_bounds__(NTHR, 1)
mega_kernel(const float* __restrict__ yp, const int* __restrict__ ytr,
            float* __restrict__ out) {
    extern __shared__ unsigned smw[];
    unsigned* Ph = smw + W_PH;
    float* s   = (float*)(smw + W_S);
    float* Bm  = (float*)(smw + W_BM);
    float* gA  = (float*)(smw + W_GA);
    float* u   = (float*)(smw + W_U);
    float* v   = (float*)(smw + W_V);
    float* w   = (float*)(smw + W_W);
    float* sp4 = (float*)(smw + W_SP);
    float* rp  = (float*)(smw + W_RP);
    float* red = (float*)(smw + W_RED);
    int*   ei  = (int*)(smw + W_EI);
    float* pw  = (float*)(smw + W_PW);
    float* AN  = (float*)(smw + W_AN);

    const int tid  = threadIdx.x;
    const int b    = blockIdx.x;
    const int lane = tid & 31;
    const int wid  = tid >> 5;

    // ---- fused global min/max of y_true (L2-hot scan) ----
    int shift;
    {
        const int4* t4 = (const int4*)ytr;
        unsigned umx = 0u, umn = 0u;
        #pragma unroll
        for (int k = 0; k < (B_DIM * N_DIM / 4) / NTHR; k++) {
            int4 x = t4[tid + k * NTHR];
            unsigned u0 = (unsigned)x.x ^ 0x80000000u;
            unsigned u1 = (unsigned)x.y ^ 0x80000000u;
            unsigned u2 = (unsigned)x.z ^ 0x80000000u;
            unsigned u3 = (unsigned)x.w ^ 0x80000000u;
            umx = max(umx, max(max(u0, u1), max(u2, u3)));
            umn = max(umn, max(max(~u0, ~u1), max(~u2, ~u3)));
        }
        for (int o = 16; o; o >>= 1) {
            umx = max(umx, __shfl_xor_sync(0xffffffffu, umx, o));
            umn = max(umn, __shfl_xor_sync(0xffffffffu, umn, o));
        }
        unsigned* ur = (unsigned*)red;
        if (lane == 0) { ur[wid] = umx; ur[16 + wid] = umn; }
        __syncthreads();
        if (tid == 0) {
            for (int k = 1; k < 16; k++) { umx = max(umx, ur[k]); umn = max(umn, ur[16 + k]); }
            red[31] = __int_as_float((int)(umx ^ 0x80000000u) + (int)((~umn) ^ 0x80000000u));
        }
        __syncthreads();
        shift = __float_as_int(red[31]);
    }

    // ---- setup: scores, flipped relevancy, gains ----
    float sj = 0.f, gain = 0.f; int e = 0;
    if (tid < 256) {
        sj = yp[b * N_DIM + tid];
        s[tid] = sj;
        e = shift - ytr[b * N_DIM + tid];
        e = min(max(e, 0), 30);
        ei[tid] = e;
        gain = (float)((1u << e) - 1u);
        gA[tid] = gain;
        u[tid] = 1.0f;
    }
    __syncthreads();

    // ---- B_mat (Kahan) + IDCG via stable rank ----
    float idcg = 0.f;
    if (tid < 256) {
        float bsum = 0.f, bc = 0.f;
        int pos = 0;
        for (int k = 0; k < N_DIM; k++) {
            float d  = fabsf(sj - s[k]);
            float y  = d - bc;
            float t2 = bsum + y;
            bc = (t2 - bsum) - y;
            bsum = t2;
            int ek = ei[k];
            pos += (ek > e) ? 1 : 0;
            pos += ((k < tid) && (ek == e)) ? 1 : 0;
        }
        Bm[tid] = bsum;
        float x = gain / log2f((float)(pos + 2));
        for (int o = 16; o; o >>= 1) x += __shfl_xor_sync(0xffffffffu, x, o);
        if (lane == 0) red[wid] = x;
    }
    __syncthreads();   // publishes Bm, red
    if (tid == 0) { for (int k = 0; k < 8; k++) idcg += red[k]; }

    // ==== P build, exp-free block scheme ====
    // Row logits: l[i][j] = s_j*(255-2i) - Bm_j  =>  l[i+k] = l[i] - 2k*s
    // => unnormalized row i+k = row i .* r^k with r_j = exp(-2 s_j).
    // 32 anchors (every 8th row) via direct softmax exp; 7 rows/block by powers.

    // r^k tables, k=0..7 (threads 0..255)
    if (tid < 256) {
        float r = __expf(-2.0f * sj);
        float pk = 1.0f;
        pw[tid] = 1.0f;
        #pragma unroll
        for (int k = 1; k < 8; k++) { pk *= r; pw[k * 256 + tid] = pk; }
    }

    // anchors: warp computes rows 8m (2 per warp), stores exp(l - rowmax) fp32
    for (int m = wid; m < 32; m += 16) {
        float sc = (float)(255 - 16 * m);
        float lg[8];
        float mxl = -3.4e38f;
        #pragma unroll
        for (int c = 0; c < 8; c++) {
            int j = c * 32 + lane;
            lg[c] = fmaf(s[j], sc, -Bm[j]);
            mxl = fmaxf(mxl, lg[c]);
        }
        for (int o = 16; o; o >>= 1) mxl = fmaxf(mxl, __shfl_xor_sync(0xffffffffu, mxl, o));
        float* an = AN + m * 256;
        #pragma unroll
        for (int c = 0; c < 8; c++) an[c * 32 + lane] = __expf(lg[c] - mxl);
    }
    __syncthreads();

    // block fill: warp per row, 16 rows/warp; normalize each row; store bf16
    __nv_bfloat16* Phb = (__nv_bfloat16*)Ph;
    #pragma unroll 1
    for (int t = 0; t < 16; t++) {
        int i = wid + 16 * t;
        const float* an = AN + (i >> 3) * 256;
        const float* pk = pw + (i & 7) * 256;
        float f[8];
        float ssum = 0.f;
        #pragma unroll
        for (int c = 0; c < 8; c++) {
            int j = c * 32 + lane;
            f[c] = an[j] * pk[j];
            ssum += f[c];
        }
        for (int o = 16; o; o >>= 1) ssum += __shfl_xor_sync(0xffffffffu, ssum, o);
        float inv = 1.0f / ssum;
        __nv_bfloat16* row = Phb + i * (2 * RSW);
        #pragma unroll
        for (int c = 0; c < 8; c++) row[c * 32 + lane] = __float2bfloat16_rn(f[c] * inv);
    }
    __syncthreads();

    // ---- Sinkhorn with early exit (unchanged from best passing kernel) ----
    const int p = tid & 127;                 // column pair (cols 2p, 2p+1)
    const int q = tid >> 7;                  // row quarter (64 rows)
    const unsigned* colp = Ph + (q * 64) * RSW + p;
    const float* uq = u + q * 64;
    const int ir = tid & 255;                // row for row pass
    const int h  = tid >> 8;                 // column half (128 cols)
    const unsigned* rowp = Ph + ir * RSW + h * 64;
    const float* vh = v + h * 128;
    float vprev = 0.f;

    for (int it = 0; it < ITERS; it++) {
        // column pass: partial over 64 rows for cols (2p, 2p+1)
        float a0 = 0.f, a1 = 0.f, a2 = 0.f, a3 = 0.f;
        #pragma unroll
        for (int i4 = 0; i4 < 16; i4++) {
            float4 uu = *(const float4*)(uq + 4 * i4);
            unsigned w0 = colp[(4 * i4 + 0) * RSW];
            unsigned w1 = colp[(4 * i4 + 1) * RSW];
            unsigned w2 = colp[(4 * i4 + 2) * RSW];
            unsigned w3 = colp[(4 * i4 + 3) * RSW];
            a0 = fmaf(bf_lo(w0), uu.x, a0); a1 = fmaf(bf_hi(w0), uu.x, a1);
            a2 = fmaf(bf_lo(w1), uu.y, a2); a3 = fmaf(bf_hi(w1), uu.y, a3);
            a0 = fmaf(bf_lo(w2), uu.z, a0); a1 = fmaf(bf_hi(w2), uu.z, a1);
            a2 = fmaf(bf_lo(w3), uu.w, a2); a3 = fmaf(bf_hi(w3), uu.w, a3);
        }
        ((float2*)sp4)[q * 128 + p] = make_float2(a0 + a2, a1 + a3);
        __syncthreads();

        // v update + convergence flag (threads 0..255)
        int ch = 0;
        if (tid < 256) {
            float S = (sp4[tid] + sp4[256 + tid]) + (sp4[512 + tid] + sp4[768 + tid]);
            float vn = 1.0f / fmaxf(S, 1e-10f);
            v[tid] = vn;
            ch = (fabsf(vn - vprev) > 1e-5f * fabsf(vprev)) ? 1 : 0;
            vprev = vn;
        }
        if (__syncthreads_or(ch) == 0) break;

        // row pass: half-row dot with v
        float r0 = 0.f, r1 = 0.f, r2 = 0.f, r3 = 0.f;
        #pragma unroll
        for (int j4 = 0; j4 < 16; j4++) {
            float4 v0 = *(const float4*)(vh + 8 * j4);
            float4 v1 = *(const float4*)(vh + 8 * j4 + 4);
            unsigned w0 = rowp[4 * j4 + 0];
            unsigned w1 = rowp[4 * j4 + 1];
            unsigned w2 = rowp[4 * j4 + 2];
            unsigned w3 = rowp[4 * j4 + 3];
            r0 = fmaf(bf_lo(w0), v0.x, r0); r1 = fmaf(bf_hi(w0), v0.y, r1);
            r2 = fmaf(bf_lo(w1), v0.z, r2); r3 = fmaf(bf_hi(w1), v0.w, r3);
            r0 = fmaf(bf_lo(w2), v1.x, r0); r1 = fmaf(bf_hi(w2), v1.y, r1);
            r2 = fmaf(bf_lo(w3), v1.z, r2); r3 = fmaf(bf_hi(w3), v1.w, r3);
        }
        rp[tid] = (r0 + r1) + (r2 + r3);
        __syncthreads();

        if (tid < 256) u[tid] = 1.0f / fmaxf(rp[tid] + rp[256 + tid], 1e-10f);
        __syncthreads();
    }

    // ---- final: num = sum_i disc_i * u_i * (P[i] . (v*g)) ----
    if (tid < 256) w[tid] = v[tid] * gA[tid];
    __syncthreads();
    {
        float r0 = 0.f, r1 = 0.f, r2 = 0.f, r3 = 0.f;
        const float* wh = w + h * 128;
        #pragma unroll
        for (int j4 = 0; j4 < 16; j4++) {
            float4 v0 = *(const float4*)(wh + 8 * j4);
            float4 v1 = *(const float4*)(wh + 8 * j4 + 4);
            unsigned w0 = rowp[4 * j4 + 0];
            unsigned w1 = rowp[4 * j4 + 1];
            unsigned w2 = rowp[4 * j4 + 2];
            unsigned w3 = rowp[4 * j4 + 3];
            r0 = fmaf(bf_lo(w0), v0.x, r0); r1 = fmaf(bf_hi(w0), v0.y, r1);
            r2 = fmaf(bf_lo(w1), v0.z, r2); r3 = fmaf(bf_hi(w1), v0.w, r3);
            r0 = fmaf(bf_lo(w2), v1.x, r0); r1 = fmaf(bf_hi(w2), v1.y, r1);
            r2 = fmaf(bf_lo(w3), v1.z, r2); r3 = fmaf(bf_hi(w3), v1.w, r3);
        }
        rp[tid] = (r0 + r1) + (r2 + r3);
    }
    __syncthreads();
    if (tid < 256) {
        float val = u[tid] * (rp[tid] + rp[256 + tid]) / log2f((float)(tid + 2));
        for (int o = 16; o; o >>= 1) val += __shfl_xor_sync(0xffffffffu, val, o);
        if (lane == 0) red[wid] = val;
    }
    __syncthreads();

    // ---- fused global reduction: atomic ticket, last CTA writes the output ----
    if (tid == 0) {
        float num = 0.f;
        for (int k = 0; k < 8; k++) num += red[k];
        bool valid = (idcg != 0.0f);
        float nd = valid ? (num / (idcg + 1e-10f)) : 0.0f;
        atomicAdd(&g_sum, nd);
        atomicAdd(&g_cnt, valid ? 1 : 0);
        __threadfence();
        unsigned tk = atomicAdd(&g_tk, 1u);
        if (tk == (unsigned)(B_DIM - 1)) {
            float sm = atomicAdd(&g_sum, 0.0f);   // all adds ordered before our ticket
            int   c  = atomicAdd(&g_cnt, 0);
            out[0] = (c > 0) ? (-(sm / (float)c)) : 0.0f;
            g_sum = 0.f;                          // reset for next graph replay
            g_cnt = 0;
            __threadfence();
            g_tk = 0u;
        }
    }
}

// ------------------------------------------------------------------ launch ---
extern "C" void kernel_launch(void* const* d_in, const int* in_sizes, int n_in,
                              void* d_out, int out_size) {
    const float* yp  = (const float*)d_in[0];
    const int*   ytr = (const int*)d_in[1];
    float*       out = (float*)d_out;

    size_t smem = (size_t)SMEM_WORDS * 4;   // 186496 B
    cudaFuncSetAttribute(mega_kernel, cudaFuncAttributeMaxDynamicSharedMemorySize, (int)smem);
    mega_kernel<<<B_DIM, NTHR, smem>>>(yp, ytr, out);
}